// round 2
// baseline (speedup 1.0000x reference)
#include <cuda_runtime.h>
#include <cstdint>

// Problem constants (static per reference: B=64, N_PER=256)
#define NPER    256u
#define EPG     65280u              // 256*255 ordered intra-graph pairs
#define NGRAPH  64u
#define ETOT    (NGRAPH * EPG)      // 4,177,920 edges

// ---------------------------------------------------------------------------
// Zero-fill for the edge_attr region: 16E floats = 16,711,680 float4 stores.
// Pure streaming STG.128.
// ---------------------------------------------------------------------------
__global__ void msb_fill_zeros(float4* __restrict__ dst, unsigned n4) {
    unsigned idx = blockIdx.x * blockDim.x + threadIdx.x;
    if (idx < n4) dst[idx] = make_float4(0.f, 0.f, 0.f, 0.f);
}

// ---------------------------------------------------------------------------
// edge_index (as float) + RBF features. One thread = 4 consecutive edges.
// All stores are aligned float4.
//   row region: out_row[e]          e in [0,E)
//   col region: out_col[e]
//   rbf region: out_rbf[3e..3e+2]   (interleaved [E,3])
// ---------------------------------------------------------------------------
__global__ void msb_edges_rbf(const float* __restrict__ pos,
                              float* __restrict__ out_row,   // may be null
                              float* __restrict__ out_col,   // may be null
                              float* __restrict__ out_rbf) { // may be null
    unsigned t = blockIdx.x * blockDim.x + threadIdx.x;
    if (t >= ETOT / 4u) return;

    float rv[4], cv[4], f[12];

#pragma unroll
    for (int k = 0; k < 4; k++) {
        unsigned e  = t * 4u + (unsigned)k;
        unsigned b  = e / EPG;            // constant-divisor -> mulhi
        unsigned l  = e - b * EPG;
        unsigned i  = l / 255u;
        unsigned jj = l - i * 255u;
        unsigned j  = jj + (jj >= i ? 1u : 0u);   // skip diagonal

        unsigned ri = b * NPER + i;
        unsigned ci = b * NPER + j;
        rv[k] = (float)ri;
        cv[k] = (float)ci;

        float ax = __ldg(pos + 3u * ri + 0u);
        float ay = __ldg(pos + 3u * ri + 1u);
        float az = __ldg(pos + 3u * ri + 2u);
        float bx = __ldg(pos + 3u * ci + 0u);
        float by = __ldg(pos + 3u * ci + 1u);
        float bz = __ldg(pos + 3u * ci + 2u);

        float dx = ax - bx, dy = ay - by, dz = az - bz;
        float d2 = fmaf(dx, dx, fmaf(dy, dy, dz * dz));

        // rbf_c = exp(-(d/c)^2) = exp(-d2/c^2), c in {4,8,12}
        f[3 * k + 0] = __expf(d2 * (-1.0f / 16.0f));
        f[3 * k + 1] = __expf(d2 * (-1.0f / 64.0f));
        f[3 * k + 2] = __expf(d2 * (-1.0f / 144.0f));
    }

    if (out_row) {
        reinterpret_cast<float4*>(out_row)[t] = make_float4(rv[0], rv[1], rv[2], rv[3]);
        reinterpret_cast<float4*>(out_col)[t] = make_float4(cv[0], cv[1], cv[2], cv[3]);
    }
    if (out_rbf) {
        float4* rb = reinterpret_cast<float4*>(out_rbf);
        rb[3u * t + 0u] = make_float4(f[0], f[1],  f[2],  f[3]);
        rb[3u * t + 1u] = make_float4(f[4], f[5],  f[6],  f[7]);
        rb[3u * t + 2u] = make_float4(f[8], f[9],  f[10], f[11]);
    }
}

// ---------------------------------------------------------------------------
// kernel_launch
// Inputs (metadata order): pos [N,3] f32, batch [N] i64 (unused),
//                          W [3,16] f32 (unused), nodes_per_graph (unused)
// Output layout (assumed concatenation of reference outputs, float32):
//   [0,E)=row  [E,2E)=col  [2E,18E)=edge_attr zeros  [18E,21E)=rbf[E,3]
// Fallbacks cover rbf-only / indices-only output conventions.
// ---------------------------------------------------------------------------
extern "C" void kernel_launch(void* const* d_in, const int* in_sizes, int n_in,
                              void* d_out, int out_size) {
    const float* pos = (const float*)d_in[0];
    float* out = (float*)d_out;

    const long long E = (long long)ETOT;
    const unsigned mainThreads = ETOT / 4u;           // 1,044,480
    const unsigned mainBlocks  = (mainThreads + 255u) / 256u;

    if ((long long)out_size == 21 * E) {
        // full layout: indices + zeros + rbf
        unsigned n4 = (unsigned)(16 * E / 4);          // 16,711,680 float4
        unsigned zBlocks = (n4 + 255u) / 256u;
        msb_fill_zeros<<<zBlocks, 256>>>((float4*)(out + 2 * E), n4);
        msb_edges_rbf<<<mainBlocks, 256>>>(pos, out, out + E, out + 18 * E);
    } else if ((long long)out_size == 3 * E) {
        // rbf only
        msb_edges_rbf<<<mainBlocks, 256>>>(pos, nullptr, nullptr, out);
    } else if ((long long)out_size == 2 * E) {
        // edge_index only
        msb_edges_rbf<<<mainBlocks, 256>>>(pos, out, out + E, nullptr);
    } else if ((long long)out_size == 5 * E) {
        // indices + rbf (no zeros region)
        msb_edges_rbf<<<mainBlocks, 256>>>(pos, out, out + E, out + 2 * E);
    } else {
        // Unknown layout: best effort — fill everything with zeros, then write
        // full layout prefix if it fits.
        long long n = out_size;
        long long n4 = n / 4;
        unsigned zBlocks = (unsigned)((n4 + 255) / 256);
        if (n4 > 0) msb_fill_zeros<<<zBlocks, 256>>>((float4*)out, (unsigned)n4);
        if (n >= 21 * E)
            msb_edges_rbf<<<mainBlocks, 256>>>(pos, out, out + E, out + 18 * E);
    }
}

// round 3
// speedup vs baseline: 1.0073x; 1.0073x over previous
#include <cuda_runtime.h>
#include <cstdint>

// Problem constants (static per reference: B=64, N_PER=256)
#define NPER    256u
#define EPG     65280u              // 256*255 ordered intra-graph pairs
#define NGRAPH  64u
#define ETOT    (NGRAPH * EPG)      // 4,177,920 edges
#define TMAIN   (ETOT / 4u)         // 1,044,480 threads, 4 edges each
#define Z4      (16u * ETOT / 4u)   // 16,711,680 float4 of zeros = 16 * TMAIN

// ---------------------------------------------------------------------------
// Fused kernel: zeros (edge_attr) + edge_index (as float) + RBF features.
// One thread = 4 consecutive edges + 16 grid-strided zero float4 stores.
// Output layout (out_size == 21E, verified by R2 pass):
//   [0,E)   row      (float-valued indices)
//   [E,2E)  col
//   [2E,18E) edge_attr zeros
//   [18E,21E) rbf [E,3] interleaved
// ---------------------------------------------------------------------------
__global__ void __launch_bounds__(256) msb_fused(const float* __restrict__ pos,
                                                 float* __restrict__ out) {
    const unsigned t = blockIdx.x * blockDim.x + threadIdx.x;
    if (t >= TMAIN) return;

    const long long E = (long long)ETOT;

    // ---- zeros first: 16 coalesced grid-strided STG.128, fire-and-forget ----
    {
        float4* __restrict__ z = reinterpret_cast<float4*>(out + 2 * E);
        const float4 zero4 = make_float4(0.f, 0.f, 0.f, 0.f);
#pragma unroll
        for (unsigned k = 0; k < 16u; k++)
            z[t + k * TMAIN] = zero4;   // stride TMAIN -> perfect warp coalescing
    }

    // ---- edge_index + rbf for 4 consecutive edges ----
    float rv[4], cv[4], f[12];

#pragma unroll
    for (int k = 0; k < 4; k++) {
        unsigned e  = t * 4u + (unsigned)k;
        unsigned b  = e / EPG;                    // constant-divisor -> mulhi
        unsigned l  = e - b * EPG;
        unsigned i  = l / 255u;
        unsigned jj = l - i * 255u;
        unsigned j  = jj + (jj >= i ? 1u : 0u);   // skip diagonal

        unsigned ri = b * NPER + i;
        unsigned ci = b * NPER + j;
        rv[k] = (float)ri;
        cv[k] = (float)ci;

        float ax = __ldg(pos + 3u * ri + 0u);
        float ay = __ldg(pos + 3u * ri + 1u);
        float az = __ldg(pos + 3u * ri + 2u);
        float bx = __ldg(pos + 3u * ci + 0u);
        float by = __ldg(pos + 3u * ci + 1u);
        float bz = __ldg(pos + 3u * ci + 2u);

        float dx = ax - bx, dy = ay - by, dz = az - bz;
        float d2 = fmaf(dx, dx, fmaf(dy, dy, dz * dz));

        // rbf_c = exp(-(d/c)^2) = exp(-d2/c^2), c in {4,8,12}
        f[3 * k + 0] = __expf(d2 * (-1.0f / 16.0f));
        f[3 * k + 1] = __expf(d2 * (-1.0f / 64.0f));
        f[3 * k + 2] = __expf(d2 * (-1.0f / 144.0f));
    }

    reinterpret_cast<float4*>(out)[t]     = make_float4(rv[0], rv[1], rv[2], rv[3]);
    reinterpret_cast<float4*>(out + E)[t] = make_float4(cv[0], cv[1], cv[2], cv[3]);

    float4* __restrict__ rb = reinterpret_cast<float4*>(out + 18 * E);
    rb[3u * t + 0u] = make_float4(f[0], f[1],  f[2],  f[3]);
    rb[3u * t + 1u] = make_float4(f[4], f[5],  f[6],  f[7]);
    rb[3u * t + 2u] = make_float4(f[8], f[9],  f[10], f[11]);
}

// ---------------------------------------------------------------------------
// Fallback zero-fill for unexpected output sizes (kept from R1, defensive).
// ---------------------------------------------------------------------------
__global__ void msb_fill_zeros(float4* __restrict__ dst, unsigned n4) {
    unsigned idx = blockIdx.x * blockDim.x + threadIdx.x;
    if (idx < n4) dst[idx] = make_float4(0.f, 0.f, 0.f, 0.f);
}

extern "C" void kernel_launch(void* const* d_in, const int* in_sizes, int n_in,
                              void* d_out, int out_size) {
    const float* pos = (const float*)d_in[0];
    float* out = (float*)d_out;

    const long long E = (long long)ETOT;
    const unsigned mainBlocks = (TMAIN + 255u) / 256u;   // 4080

    if ((long long)out_size == 21 * E) {
        msb_fused<<<mainBlocks, 256>>>(pos, out);
    } else {
        // Unknown layout: zero everything (best effort, keeps determinism).
        long long n4 = (long long)out_size / 4;
        if (n4 > 0) {
            unsigned zBlocks = (unsigned)((n4 + 255) / 256);
            msb_fill_zeros<<<zBlocks, 256>>>((float4*)out, (unsigned)n4);
        }
    }
}

// round 4
// speedup vs baseline: 1.0416x; 1.0341x over previous
#include <cuda_runtime.h>
#include <cstdint>

// Problem constants (static per reference: B=64, N_PER=256)
#define NPER    256u
#define EPG     65280u              // 256*255 ordered intra-graph pairs
#define NGRAPH  64u
#define ETOT    (NGRAPH * EPG)      // 4,177,920 edges
#define TMAIN   (ETOT / 4u)         // 1,044,480 threads, 4 edges each
#define NBLK    (TMAIN / 256u)      // 4080 blocks, exact

// ---------------------------------------------------------------------------
// Fused kernel: zeros (edge_attr) + edge_index (as float) + RBF features.
// One thread = 4 consecutive edges + 16 grid-strided zero float4 stores,
// interleaved 4-per-edge-iteration to keep DRAM demand smooth.
// pos is staged in shared memory (block spans <= 2 graphs).
// Output layout (out_size == 21E):
//   [0,E) row | [E,2E) col | [2E,18E) zeros | [18E,21E) rbf[E,3]
// ---------------------------------------------------------------------------
__global__ void __launch_bounds__(256) msb_fused(const float* __restrict__ pos,
                                                 float* __restrict__ out) {
    __shared__ float sp[1536];                 // 2 graphs x 256 nodes x 3 floats

    const unsigned tid = threadIdx.x;
    const unsigned t   = blockIdx.x * 256u + tid;     // grid is exactly TMAIN
    const unsigned e0b = blockIdx.x * 1024u;          // first edge of block
    const unsigned b0  = e0b / EPG;
    const unsigned b1  = (e0b + 1023u) / EPG;         // b1 == b0 or b0+1

    // ---- cooperative load of pos slices for graphs b0 (and b1) ----
    const float4* p4 = reinterpret_cast<const float4*>(pos);  // 192 float4/graph
    if (tid < 192u)
        reinterpret_cast<float4*>(sp)[tid] = p4[b0 * 192u + tid];
    if (b1 != b0 && tid >= 64u)
        reinterpret_cast<float4*>(sp + 768)[tid - 64u] = p4[b1 * 192u + (tid - 64u)];
    __syncthreads();

    const long long E = (long long)ETOT;
    float4* __restrict__ z = reinterpret_cast<float4*>(out + 2 * E);
    const float4 zero4 = make_float4(0.f, 0.f, 0.f, 0.f);

    float rv[4], cv[4], f[12];

#pragma unroll
    for (int k = 0; k < 4; k++) {
        // ---- 4 interleaved zero stores (coalesced, streaming) ----
#pragma unroll
        for (int q = 0; q < 4; q++)
            __stcs(&z[t + (unsigned)(4 * k + q) * TMAIN], zero4);

        // ---- edge (b,i,j) decomposition ----
        unsigned e  = t * 4u + (unsigned)k;
        unsigned b  = e / EPG;                    // constant-divisor -> mulhi
        unsigned l  = e - b * EPG;
        unsigned i  = l / 255u;
        unsigned jj = l - i * 255u;
        unsigned j  = jj + (jj >= i ? 1u : 0u);   // skip diagonal

        rv[k] = (float)(b * NPER + i);
        cv[k] = (float)(b * NPER + j);

        const float* sb = sp + (b == b0 ? 0 : 768);
        float ax = sb[3u * i + 0u];               // broadcast across warp (mostly)
        float ay = sb[3u * i + 1u];
        float az = sb[3u * i + 2u];
        float bx = sb[3u * j + 0u];               // stride-3 lanes: conflict-free
        float by = sb[3u * j + 1u];
        float bz = sb[3u * j + 2u];

        float dx = ax - bx, dy = ay - by, dz = az - bz;
        float d2 = fmaf(dx, dx, fmaf(dy, dy, dz * dz));

        // rbf_c = exp(-(d/c)^2) = exp(-d2/c^2), c in {4,8,12}
        f[3 * k + 0] = __expf(d2 * (-1.0f / 16.0f));
        f[3 * k + 1] = __expf(d2 * (-1.0f / 64.0f));
        f[3 * k + 2] = __expf(d2 * (-1.0f / 144.0f));
    }

    __stcs(&reinterpret_cast<float4*>(out)[t],
           make_float4(rv[0], rv[1], rv[2], rv[3]));
    __stcs(&reinterpret_cast<float4*>(out + E)[t],
           make_float4(cv[0], cv[1], cv[2], cv[3]));

    float4* __restrict__ rb = reinterpret_cast<float4*>(out + 18 * E);
    __stcs(&rb[3u * t + 0u], make_float4(f[0], f[1],  f[2],  f[3]));
    __stcs(&rb[3u * t + 1u], make_float4(f[4], f[5],  f[6],  f[7]));
    __stcs(&rb[3u * t + 2u], make_float4(f[8], f[9],  f[10], f[11]));
}

// ---------------------------------------------------------------------------
// Fallback zero-fill for unexpected output sizes (defensive).
// ---------------------------------------------------------------------------
__global__ void msb_fill_zeros(float4* __restrict__ dst, unsigned n4) {
    unsigned idx = blockIdx.x * blockDim.x + threadIdx.x;
    if (idx < n4) dst[idx] = make_float4(0.f, 0.f, 0.f, 0.f);
}

extern "C" void kernel_launch(void* const* d_in, const int* in_sizes, int n_in,
                              void* d_out, int out_size) {
    const float* pos = (const float*)d_in[0];
    float* out = (float*)d_out;

    const long long E = (long long)ETOT;

    if ((long long)out_size == 21 * E) {
        msb_fused<<<NBLK, 256>>>(pos, out);
    } else {
        long long n4 = (long long)out_size / 4;
        if (n4 > 0) {
            unsigned zBlocks = (unsigned)((n4 + 255) / 256);
            msb_fill_zeros<<<zBlocks, 256>>>((float4*)out, (unsigned)n4);
        }
    }
}